// round 1
// baseline (speedup 1.0000x reference)
#include <cuda_runtime.h>
#include <math.h>

// GeometricAttention: full softmax attention, d = 144 (128 "mv" + 16 "s"),
// BH = 32 heads, N = 2048, scale = 1/12. IPF sign pattern folded into Q load.
//
// fp32 SIMT flash attention baseline:
//   grid = (N/64 q-tiles, BH), 256 threads/block, BQ=64, BK=32.
//   Thread (ty,tx) in 16x16 layout owns S rows {ty+16i}, cols {tx+16j}.
//   O fragment 4x9 (cols tx+16j, j<9 covers all 144 dims; j==8 is the "s" slice).
//   Smem strides 145 (Q/K/V) and 33 (P) -> conflict-free inner-loop LDS.

#define BQ   64
#define BK   32
#define DDIM 144
#define NSEQ 2048
#define BHN  32
#define QSTR 145
#define KSTR 145
#define PSTR 33
#define NF4  36            // 144 floats = 36 float4 per row
#define SCALE (1.0f/12.0f)

#define SMEM_FLOATS (BQ*QSTR + 2*BK*KSTR + BQ*PSTR)
#define SMEM_BYTES  (SMEM_FLOATS * 4)

__constant__ float c_ipf[16] = {1.f,1.f,-1.f,-1.f,-1.f,-1.f,-1.f,-1.f,
                                1.f,1.f, 1.f, 1.f, 1.f, 1.f,-1.f,-1.f};

extern "C" __global__ void __launch_bounds__(256, 2)
geo_attn_kernel(const float* __restrict__ q_mv, const float* __restrict__ k_mv,
                const float* __restrict__ v_mv, const float* __restrict__ q_s,
                const float* __restrict__ k_s,  const float* __restrict__ v_s,
                float* __restrict__ out_mv, float* __restrict__ out_s)
{
    extern __shared__ float sm[];
    float* Qs = sm;                       // [64][145]
    float* Ks = Qs + BQ * QSTR;           // [32][145]
    float* Vs = Ks + BK * KSTR;           // [32][145]
    float* Ps = Vs + BK * KSTR;           // [64][33]

    const int tid = threadIdx.x;
    const int tx  = tid & 15;
    const int ty  = tid >> 4;
    const int bh  = blockIdx.y;
    const int qbase = blockIdx.x * BQ;

    const float* qmv_b = q_mv + (size_t)bh * NSEQ * 128;
    const float* qs_b  = q_s  + (size_t)bh * NSEQ * 16;
    const float* kmv_b = k_mv + (size_t)bh * NSEQ * 128;
    const float* ks_b  = k_s  + (size_t)bh * NSEQ * 16;
    const float* vmv_b = v_mv + (size_t)bh * NSEQ * 128;
    const float* vs_b  = v_s  + (size_t)bh * NSEQ * 16;

    // ---- Load Q tile: apply IPF sign and fold in scale -----------------
    for (int i4 = tid; i4 < BQ * NF4; i4 += 256) {
        int row = i4 / NF4;
        int c4  = i4 % NF4;
        int n   = qbase + row;
        float4 v;
        if (c4 < 32) {
            v = *(const float4*)(qmv_b + (size_t)n * 128 + c4 * 4);
            int sg = (c4 & 3) * 4;           // position within the 16-wide sign pattern
            v.x *= c_ipf[sg + 0] * SCALE;
            v.y *= c_ipf[sg + 1] * SCALE;
            v.z *= c_ipf[sg + 2] * SCALE;
            v.w *= c_ipf[sg + 3] * SCALE;
        } else {
            v = *(const float4*)(qs_b + (size_t)n * 16 + (c4 - 32) * 4);
            v.x *= SCALE; v.y *= SCALE; v.z *= SCALE; v.w *= SCALE;
        }
        float* dst = Qs + row * QSTR + c4 * 4;
        dst[0] = v.x; dst[1] = v.y; dst[2] = v.z; dst[3] = v.w;
    }

    float acc[4][9];
    float m_i[4], l_i[4];
    #pragma unroll
    for (int i = 0; i < 4; i++) {
        m_i[i] = -INFINITY;
        l_i[i] = 0.f;
        #pragma unroll
        for (int j = 0; j < 9; j++) acc[i][j] = 0.f;
    }

    for (int kt = 0; kt < NSEQ / BK; kt++) {
        __syncthreads();   // prev-iter PV reads of Ks/Vs/Ps done (also fences Q load at kt=0)
        const int kbase = kt * BK;

        // ---- Load K/V tiles --------------------------------------------
        for (int i4 = tid; i4 < BK * NF4; i4 += 256) {
            int row = i4 / NF4;
            int c4  = i4 % NF4;
            int n   = kbase + row;
            float4 kv, vv;
            if (c4 < 32) {
                kv = *(const float4*)(kmv_b + (size_t)n * 128 + c4 * 4);
                vv = *(const float4*)(vmv_b + (size_t)n * 128 + c4 * 4);
            } else {
                kv = *(const float4*)(ks_b + (size_t)n * 16 + (c4 - 32) * 4);
                vv = *(const float4*)(vs_b + (size_t)n * 16 + (c4 - 32) * 4);
            }
            float* kd = Ks + row * KSTR + c4 * 4;
            kd[0] = kv.x; kd[1] = kv.y; kd[2] = kv.z; kd[3] = kv.w;
            float* vd = Vs + row * KSTR + c4 * 4;
            vd[0] = vv.x; vd[1] = vv.y; vd[2] = vv.z; vd[3] = vv.w;
        }
        __syncthreads();

        // ---- S = Q K^T fragment (4 rows x 2 cols per thread) -----------
        float s_[4][2];
        #pragma unroll
        for (int i = 0; i < 4; i++) { s_[i][0] = 0.f; s_[i][1] = 0.f; }

        const float* qp  = Qs + ty * QSTR;
        const float* kp0 = Ks + tx * KSTR;
        const float* kp1 = Ks + (tx + 16) * KSTR;
        #pragma unroll 4
        for (int d = 0; d < DDIM; d++) {
            float k0 = kp0[d];
            float k1 = kp1[d];
            float q0 = qp[d];
            float q1 = qp[16 * QSTR + d];
            float q2 = qp[32 * QSTR + d];
            float q3 = qp[48 * QSTR + d];
            s_[0][0] += q0 * k0;  s_[0][1] += q0 * k1;
            s_[1][0] += q1 * k0;  s_[1][1] += q1 * k1;
            s_[2][0] += q2 * k0;  s_[2][1] += q2 * k1;
            s_[3][0] += q3 * k0;  s_[3][1] += q3 * k1;
        }

        // ---- Online softmax (row stats reduced across the 16 tx lanes) --
        #pragma unroll
        for (int i = 0; i < 4; i++) {
            float mx = fmaxf(s_[i][0], s_[i][1]);
            #pragma unroll
            for (int off = 8; off > 0; off >>= 1)
                mx = fmaxf(mx, __shfl_xor_sync(0xffffffffu, mx, off));
            float mn    = fmaxf(m_i[i], mx);
            float alpha = (m_i[i] == -INFINITY) ? 0.f : __expf(m_i[i] - mn);
            float p0 = __expf(s_[i][0] - mn);
            float p1 = __expf(s_[i][1] - mn);
            float rs = p0 + p1;
            #pragma unroll
            for (int off = 8; off > 0; off >>= 1)
                rs += __shfl_xor_sync(0xffffffffu, rs, off);
            l_i[i] = l_i[i] * alpha + rs;
            m_i[i] = mn;
            Ps[(ty + 16 * i) * PSTR + tx]      = p0;
            Ps[(ty + 16 * i) * PSTR + tx + 16] = p1;
            #pragma unroll
            for (int j = 0; j < 9; j++) acc[i][j] *= alpha;
        }
        __syncthreads();

        // ---- O += P V (9 output cols per thread: tx + 16j) -------------
        #pragma unroll 2
        for (int c = 0; c < BK; c++) {
            float p0 = Ps[ty        * PSTR + c];
            float p1 = Ps[(ty + 16) * PSTR + c];
            float p2 = Ps[(ty + 32) * PSTR + c];
            float p3 = Ps[(ty + 48) * PSTR + c];
            const float* vp = Vs + c * KSTR + tx;
            #pragma unroll
            for (int j = 0; j < 9; j++) {
                float vv = vp[16 * j];
                acc[0][j] += p0 * vv;
                acc[1][j] += p1 * vv;
                acc[2][j] += p2 * vv;
                acc[3][j] += p3 * vv;
            }
        }
    }

    // ---- Epilogue: normalize and scatter to out_mv / out_s -------------
    #pragma unroll
    for (int i = 0; i < 4; i++) {
        float inv = 1.f / l_i[i];
        int n = qbase + ty + 16 * i;
        size_t rbase = (size_t)bh * NSEQ + n;
        #pragma unroll
        for (int j = 0; j < 9; j++) {
            float val = acc[i][j] * inv;
            if (j < 8) out_mv[rbase * 128 + (tx + 16 * j)] = val;
            else       out_s[rbase * 16 + tx] = val;
        }
    }
}

extern "C" void kernel_launch(void* const* d_in, const int* in_sizes, int n_in,
                              void* d_out, int out_size)
{
    const float* q_mv = (const float*)d_in[0];
    const float* k_mv = (const float*)d_in[1];
    const float* v_mv = (const float*)d_in[2];
    const float* q_s  = (const float*)d_in[3];
    const float* k_s  = (const float*)d_in[4];
    const float* v_s  = (const float*)d_in[5];

    float* out_mv = (float*)d_out;
    float* out_s  = out_mv + (size_t)BHN * NSEQ * 128;

    // Idempotent, deterministic; needed because 82.7 KB dynamic smem > 48 KB default.
    cudaFuncSetAttribute(geo_attn_kernel,
                         cudaFuncAttributeMaxDynamicSharedMemorySize, SMEM_BYTES);

    dim3 grid(NSEQ / BQ, BHN);
    geo_attn_kernel<<<grid, 256, SMEM_BYTES>>>(q_mv, k_mv, v_mv, q_s, k_s, v_s,
                                               out_mv, out_s);
}

// round 2
// speedup vs baseline: 3.0602x; 3.0602x over previous
#include <cuda_runtime.h>
#include <math.h>

// GeometricAttention, tf32 mma.sync flash attention.
// d=144, N=2048, BH=32, scale=1/12 (folded into Q with the IPF signs).
// BQ=128 (8 warps x 16 rows), BK=64. Per warp: S = 8 m16n8 tiles over 18 k8
// steps; softmax in registers; P -> smem (tf32) -> A-frags; O += P*V over
// 18 d-tiles x 8 k-steps. All accumulation fp32.

#define BQ   128
#define BK   64
#define DDIM 144
#define NSEQ 2048
#define BHN  32
#define QSTR 148          // A-pattern stride: = 4 mod 8 -> conflict-free
#define KSTR 148
#define VSTR 152          // V B-pattern stride: = 8 mod 16 -> conflict-free
#define PSTR 68
#define NKS  18           // DDIM/8
#define NTS  8            // BK/8
#define NTD  18           // DDIM/8
#define NF4  36
#define SCALE (1.0f/12.0f)

#define SMEM_FLOATS (BQ*QSTR + BK*KSTR + BK*VSTR + BQ*PSTR)
#define SMEM_BYTES  (SMEM_FLOATS * 4)

__constant__ float c_ipf[16] = {1.f,1.f,-1.f,-1.f,-1.f,-1.f,-1.f,-1.f,
                                1.f,1.f, 1.f, 1.f, 1.f, 1.f,-1.f,-1.f};

__device__ __forceinline__ unsigned tf32r(float x) {
    unsigned r; asm("cvt.rna.tf32.f32 %0, %1;" : "=r"(r) : "f"(x)); return r;
}
__device__ __forceinline__ float tf32f(float x) { return __uint_as_float(tf32r(x)); }

__device__ __forceinline__ void mma8(float c[4], unsigned a0, unsigned a1,
                                     unsigned a2, unsigned a3,
                                     unsigned b0, unsigned b1) {
    asm volatile(
        "mma.sync.aligned.m16n8k8.row.col.f32.tf32.tf32.f32 "
        "{%0,%1,%2,%3}, {%4,%5,%6,%7}, {%8,%9}, {%0,%1,%2,%3};"
        : "+f"(c[0]), "+f"(c[1]), "+f"(c[2]), "+f"(c[3])
        : "r"(a0), "r"(a1), "r"(a2), "r"(a3), "r"(b0), "r"(b1));
}

extern "C" __global__ void __launch_bounds__(256, 1)
geo_attn_tf32(const float* __restrict__ q_mv, const float* __restrict__ k_mv,
              const float* __restrict__ v_mv, const float* __restrict__ q_s,
              const float* __restrict__ k_s,  const float* __restrict__ v_s,
              float* __restrict__ out_mv, float* __restrict__ out_s)
{
    extern __shared__ float sm[];
    float* Qs = sm;                       // [128][148]
    float* Ks = Qs + BQ * QSTR;           // [64][148]
    float* Vs = Ks + BK * KSTR;           // [64][152]
    float* Ps = Vs + BK * VSTR;           // [128][68]

    const int tid  = threadIdx.x;
    const int lane = tid & 31;
    const int warp = tid >> 5;
    const int g    = lane >> 2;           // groupID (0..7)
    const int t4   = lane & 3;            // threadID_in_group (0..3)
    const int bh   = blockIdx.y;
    const int qbase = blockIdx.x * BQ;
    const int qrow  = warp * 16 + g;      // local row of fragment row 0

    const float* qmv_b = q_mv + (size_t)bh * NSEQ * 128;
    const float* qs_b  = q_s  + (size_t)bh * NSEQ * 16;
    const float* kmv_b = k_mv + (size_t)bh * NSEQ * 128;
    const float* ks_b  = k_s  + (size_t)bh * NSEQ * 16;
    const float* vmv_b = v_mv + (size_t)bh * NSEQ * 128;
    const float* vs_b  = v_s  + (size_t)bh * NSEQ * 16;

    // ---- Q tile: IPF sign * scale, round to tf32, store -----------------
    for (int i4 = tid; i4 < BQ * NF4; i4 += 256) {
        int row = i4 / NF4, c4 = i4 % NF4;
        int n = qbase + row;
        float4 v;
        if (c4 < 32) {
            v = *(const float4*)(qmv_b + (size_t)n * 128 + c4 * 4);
            int sg = (c4 & 3) * 4;
            v.x *= c_ipf[sg + 0] * SCALE;  v.y *= c_ipf[sg + 1] * SCALE;
            v.z *= c_ipf[sg + 2] * SCALE;  v.w *= c_ipf[sg + 3] * SCALE;
        } else {
            v = *(const float4*)(qs_b + (size_t)n * 16 + (c4 - 32) * 4);
            v.x *= SCALE; v.y *= SCALE; v.z *= SCALE; v.w *= SCALE;
        }
        float* dst = Qs + row * QSTR + c4 * 4;
        dst[0] = tf32f(v.x); dst[1] = tf32f(v.y);
        dst[2] = tf32f(v.z); dst[3] = tf32f(v.w);
    }

    float o[NTD][4];
    #pragma unroll
    for (int t = 0; t < NTD; t++) { o[t][0]=0.f; o[t][1]=0.f; o[t][2]=0.f; o[t][3]=0.f; }
    float m0 = -INFINITY, m1 = -INFINITY, l0 = 0.f, l1 = 0.f;

    for (int kt = 0; kt < NSEQ / BK; kt++) {
        __syncthreads();                      // K/V/Q stores visible / reuse safe
        const int kbase = kt * BK;

        for (int i4 = tid; i4 < BK * NF4; i4 += 256) {
            int row = i4 / NF4, c4 = i4 % NF4;
            int n = kbase + row;
            float4 kv, vv;
            if (c4 < 32) {
                kv = *(const float4*)(kmv_b + (size_t)n * 128 + c4 * 4);
                vv = *(const float4*)(vmv_b + (size_t)n * 128 + c4 * 4);
            } else {
                kv = *(const float4*)(ks_b + (size_t)n * 16 + (c4 - 32) * 4);
                vv = *(const float4*)(vs_b + (size_t)n * 16 + (c4 - 32) * 4);
            }
            float* kd = Ks + row * KSTR + c4 * 4;
            kd[0]=tf32f(kv.x); kd[1]=tf32f(kv.y); kd[2]=tf32f(kv.z); kd[3]=tf32f(kv.w);
            float* vd = Vs + row * VSTR + c4 * 4;
            vd[0]=tf32f(vv.x); vd[1]=tf32f(vv.y); vd[2]=tf32f(vv.z); vd[3]=tf32f(vv.w);
        }
        __syncthreads();

        // ---- S = Q K^T : 8 m16n8 tiles, 18 k8 steps --------------------
        float s[NTS][4];
        #pragma unroll
        for (int t = 0; t < NTS; t++) { s[t][0]=0.f; s[t][1]=0.f; s[t][2]=0.f; s[t][3]=0.f; }

        for (int ks = 0; ks < NKS; ks++) {
            const float* qp = Qs + qrow * QSTR + ks * 8 + t4;
            unsigned a0 = __float_as_uint(qp[0]);
            unsigned a1 = __float_as_uint(qp[8 * QSTR]);
            unsigned a2 = __float_as_uint(qp[4]);
            unsigned a3 = __float_as_uint(qp[8 * QSTR + 4]);
            #pragma unroll
            for (int t = 0; t < NTS; t++) {
                const float* kp = Ks + (t * 8 + g) * KSTR + ks * 8 + t4;
                unsigned b0 = __float_as_uint(kp[0]);
                unsigned b1 = __float_as_uint(kp[4]);
                mma8(s[t], a0, a1, a2, a3, b0, b1);
            }
        }

        // ---- online softmax (quad = one row) ---------------------------
        float mx0 = -INFINITY, mx1 = -INFINITY;
        #pragma unroll
        for (int t = 0; t < NTS; t++) {
            mx0 = fmaxf(mx0, fmaxf(s[t][0], s[t][1]));
            mx1 = fmaxf(mx1, fmaxf(s[t][2], s[t][3]));
        }
        mx0 = fmaxf(mx0, __shfl_xor_sync(0xffffffffu, mx0, 1));
        mx0 = fmaxf(mx0, __shfl_xor_sync(0xffffffffu, mx0, 2));
        mx1 = fmaxf(mx1, __shfl_xor_sync(0xffffffffu, mx1, 1));
        mx1 = fmaxf(mx1, __shfl_xor_sync(0xffffffffu, mx1, 2));

        float mn0 = fmaxf(m0, mx0), mn1 = fmaxf(m1, mx1);
        float al0 = __expf(m0 - mn0), al1 = __expf(m1 - mn1);
        float sum0 = 0.f, sum1 = 0.f;
        #pragma unroll
        for (int t = 0; t < NTS; t++) {
            s[t][0] = __expf(s[t][0] - mn0);
            s[t][1] = __expf(s[t][1] - mn0);
            s[t][2] = __expf(s[t][2] - mn1);
            s[t][3] = __expf(s[t][3] - mn1);
            sum0 += s[t][0] + s[t][1];
            sum1 += s[t][2] + s[t][3];
        }
        sum0 += __shfl_xor_sync(0xffffffffu, sum0, 1);
        sum0 += __shfl_xor_sync(0xffffffffu, sum0, 2);
        sum1 += __shfl_xor_sync(0xffffffffu, sum1, 1);
        sum1 += __shfl_xor_sync(0xffffffffu, sum1, 2);
        l0 = l0 * al0 + sum0;  m0 = mn0;
        l1 = l1 * al1 + sum1;  m1 = mn1;

        #pragma unroll
        for (int t = 0; t < NTD; t++) {
            o[t][0] *= al0; o[t][1] *= al0; o[t][2] *= al1; o[t][3] *= al1;
        }

        // ---- P -> smem (tf32), per-warp private region -----------------
        #pragma unroll
        for (int t = 0; t < NTS; t++) {
            float2 v0; v0.x = tf32f(s[t][0]); v0.y = tf32f(s[t][1]);
            *(float2*)(Ps + qrow * PSTR + t * 8 + 2 * t4) = v0;
            float2 v1; v1.x = tf32f(s[t][2]); v1.y = tf32f(s[t][3]);
            *(float2*)(Ps + (qrow + 8) * PSTR + t * 8 + 2 * t4) = v1;
        }
        __syncwarp();

        // ---- O += P V : 18 d-tiles, 8 k8 steps -------------------------
        for (int ks = 0; ks < NTS; ks++) {
            const float* pp = Ps + qrow * PSTR + ks * 8 + t4;
            unsigned a0 = __float_as_uint(pp[0]);
            unsigned a1 = __float_as_uint(pp[8 * PSTR]);
            unsigned a2 = __float_as_uint(pp[4]);
            unsigned a3 = __float_as_uint(pp[8 * PSTR + 4]);
            #pragma unroll
            for (int t = 0; t < NTD; t++) {
                const float* vp = Vs + (ks * 8 + t4) * VSTR + t * 8 + g;
                unsigned b0 = __float_as_uint(vp[0]);
                unsigned b1 = __float_as_uint(vp[4 * VSTR]);
                mma8(o[t], a0, a1, a2, a3, b0, b1);
            }
        }
    }

    // ---- epilogue --------------------------------------------------------
    float inv0 = 1.f / l0, inv1 = 1.f / l1;
    int r0 = qbase + qrow, r1 = r0 + 8;
    size_t rb0 = (size_t)bh * NSEQ + r0;
    size_t rb1 = (size_t)bh * NSEQ + r1;
    #pragma unroll
    for (int t = 0; t < NTD; t++) {
        int col = t * 8 + 2 * t4;
        float2 w0; w0.x = o[t][0] * inv0; w0.y = o[t][1] * inv0;
        float2 w1; w1.x = o[t][2] * inv1; w1.y = o[t][3] * inv1;
        if (t < 16) {
            *(float2*)(out_mv + rb0 * 128 + col) = w0;
            *(float2*)(out_mv + rb1 * 128 + col) = w1;
        } else {
            int sc = (t - 16) * 8 + 2 * t4;
            *(float2*)(out_s + rb0 * 16 + sc) = w0;
            *(float2*)(out_s + rb1 * 16 + sc) = w1;
        }
    }
}

extern "C" void kernel_launch(void* const* d_in, const int* in_sizes, int n_in,
                              void* d_out, int out_size)
{
    const float* q_mv = (const float*)d_in[0];
    const float* k_mv = (const float*)d_in[1];
    const float* v_mv = (const float*)d_in[2];
    const float* q_s  = (const float*)d_in[3];
    const float* k_s  = (const float*)d_in[4];
    const float* v_s  = (const float*)d_in[5];

    float* out_mv = (float*)d_out;
    float* out_s  = out_mv + (size_t)BHN * NSEQ * 128;

    cudaFuncSetAttribute(geo_attn_tf32,
                         cudaFuncAttributeMaxDynamicSharedMemorySize, SMEM_BYTES);

    dim3 grid(NSEQ / BQ, BHN);
    geo_attn_tf32<<<grid, 256, SMEM_BYTES>>>(q_mv, k_mv, v_mv, q_s, k_s, v_s,
                                             out_mv, out_s);
}